// round 8
// baseline (speedup 1.0000x reference)
#include <cuda_runtime.h>
#include <cstdint>

// Problem constants (fixed by the reference: T=8, x shape [T*32, 128, 32, 32])
#define T_STEPS   8
#define BATCH     32
#define CHANNELS  128
#define HW        1024                      // 32*32
#define N_ELEM    (BATCH*CHANNELS*HW)       // 4,194,304 spatial positions
#define NUM_SLABS 4096
#define GRID1     256                       // single wave at 2 blocks/SM (296 slots)
#define ITERS     8                         // block handles 16 slabs: {b+256j, b+256j+2048}

// Scratch (static device globals — no runtime allocation permitted).
// Barrier counters are MONOTONIC across graph replays (each replay consumes
// exactly GRID1 arrivals / 1 release) -> no reset, fully deterministic.
__device__ float    g_partials[GRID1];      // per-block sum; channel = bid % 128
__device__ float    g_scale;
__device__ unsigned g_arrive  = 0;
__device__ unsigned g_release = 0;

// 256-bit global accesses (sm_100): 8 floats per instruction.
struct F8 { float v[8]; };

__device__ __forceinline__ F8 ld256_stream(const float* p) {
    uint32_t a,b,c,d,e,f,g,h;
    asm volatile("ld.global.nc.L2::evict_first.v8.b32 {%0,%1,%2,%3,%4,%5,%6,%7}, [%8];"
                 : "=r"(a),"=r"(b),"=r"(c),"=r"(d),"=r"(e),"=r"(f),"=r"(g),"=r"(h)
                 : "l"(p));
    F8 r;
    r.v[0]=__uint_as_float(a); r.v[1]=__uint_as_float(b);
    r.v[2]=__uint_as_float(c); r.v[3]=__uint_as_float(d);
    r.v[4]=__uint_as_float(e); r.v[5]=__uint_as_float(f);
    r.v[6]=__uint_as_float(g); r.v[7]=__uint_as_float(h);
    return r;
}

__device__ __forceinline__ void st256_resident(float* p, const float* v) {
    asm volatile("st.global.L2::evict_last.v8.b32 [%0], {%1,%2,%3,%4,%5,%6,%7,%8};"
                 :: "l"(p),
                    "r"(__float_as_uint(v[0])), "r"(__float_as_uint(v[1])),
                    "r"(__float_as_uint(v[2])), "r"(__float_as_uint(v[3])),
                    "r"(__float_as_uint(v[4])), "r"(__float_as_uint(v[5])),
                    "r"(__float_as_uint(v[6])), "r"(__float_as_uint(v[7]))
                 : "memory");
}

// Block-wide deterministic sum (256 threads): shuffle tree + one smem hop.
__device__ __forceinline__ float block_sum_256(float v, float* ws) {
#pragma unroll
    for (int off = 16; off > 0; off >>= 1)
        v += __shfl_down_sync(0xFFFFFFFFu, v, off);
    const int wid = threadIdx.x >> 5;
    if ((threadIdx.x & 31) == 0) ws[wid] = v;
    __syncthreads();
    if (wid == 0) {
        v = (threadIdx.x < 8) ? ws[threadIdx.x] : 0.0f;
#pragma unroll
        for (int off = 4; off > 0; off >>= 1)
            v += __shfl_down_sync(0xFFFFFFFFu, v, off);
    }
    __syncthreads();
    return v;                 // valid in thread 0
}

// ---------------------------------------------------------------------------
// Fused persistent kernel, 256-bit memory ops:
//   Phase A: IF recurrence (8 elems/thread), spike bits -> smem, partial sum.
//   Grid barrier: last arriver computes the global scalar scale.
//   Phase B: expand bits * scale with 256-bit stores.
// ---------------------------------------------------------------------------
__global__ __launch_bounds__(256, 2) void if_fused(const float* __restrict__ x,
                                                   const float* __restrict__ thresh,
                                                   float* __restrict__ out) {
    __shared__ uint32_t s_bits[ITERS][256][2];   // 16 KiB: per-thread 64 spike bits
    __shared__ float    s_ws[8];
    __shared__ float    s_scale;
    __shared__ unsigned s_gen;
    __shared__ int      s_last;

    const float thre    = __ldg(thresh);
    const int   half    = threadIdx.x >> 7;      // 0: slab b+256j, 1: +2048
    const int   lane128 = threadIdx.x & 127;
    float local = 0.0f;

    // ---- Phase A ----
#pragma unroll 1
    for (int j = 0; j < ITERS; j++) {
        const int slab = blockIdx.x + j * GRID1 + half * 2048;   // channel = bid%128
        const int n    = slab * HW + lane128 * 8;

        F8 xv[T_STEPS];                          // 8 independent 256-bit loads
#pragma unroll
        for (int t = 0; t < T_STEPS; t++)
            xv[t] = ld256_stream(x + (size_t)t * N_ELEM + n);

        float mem[8];
#pragma unroll
        for (int e = 0; e < 8; e++) mem[e] = 0.5f * thre;
        uint32_t sbl = 0u, sbh = 0u;             // bits: elem e, t -> bit (t + 8*(e&3))

#pragma unroll
        for (int t = 0; t < T_STEPS; t++) {
#pragma unroll
            for (int e = 0; e < 8; e++) {
                mem[e] += xv[t].v[e];
                if (mem[e] >= thre) {            // heaviside(mem - cur)
                    mem[e] -= thre;              // mem -= s*cur
                    if (e < 4) sbl |= 1u << (t + 8 * e);
                    else       sbh |= 1u << (t + 8 * (e - 4));
                }
            }
        }

        s_bits[j][threadIdx.x][0] = sbl;
        s_bits[j][threadIdx.x][1] = sbh;

        // Compensation pass -> per-element new_thre (cnt via popc).
#pragma unroll
        for (int e = 0; e < 8; e++) {
            const uint32_t byte = ((e < 4 ? sbl : sbh) >> (8 * (e & 3))) & 0xFFu;
            const int      cnt  = __popc(byte);
            const float    cv   = fminf((mem[e] - 0.5f * thre) + (float)cnt * thre,
                                        (float)T_STEPS * thre);
            if (cv > 0.0f && cnt > 0)
                local += cv / (float)cnt;
        }
    }

    const float total = block_sum_256(local, s_ws);

    // ---- Grid barrier (generation-counted, monotonic across replays) ----
    if (threadIdx.x == 0) {
        g_partials[blockIdx.x] = total;
        __threadfence();
        const unsigned old = atomicAdd(&g_arrive, 1u);
        s_gen  = old / GRID1;
        s_last = ((old % GRID1) == GRID1 - 1);
    }
    __syncthreads();

    if (s_last) {
        // channel c's 32 slabs live in partials[c] (16) + partials[c+128] (16).
        float contrib = 0.0f;
        if (threadIdx.x < CHANNELS) {
            const float s  = g_partials[threadIdx.x] + g_partials[threadIdx.x + CHANNELS];
            const float ub = s / (float)(BATCH * HW);
            contrib = (thre > ub) ? (ub - thre) : 0.0f;
        }
        const float tot = block_sum_256(contrib, s_ws);
        if (threadIdx.x == 0) {
            g_scale = thre + 0.2f * tot / (float)CHANNELS;    // LR*2 = 0.2
            __threadfence();
            atomicAdd(&g_release, 1u);
        }
    }

    if (threadIdx.x == 0) {
        const unsigned target = s_gen + 1u;
        unsigned v;
        do {
            asm volatile("ld.acquire.gpu.u32 %0, [%1];" : "=r"(v) : "l"(&g_release));
        } while (v < target);
        s_scale = g_scale;
    }
    __syncthreads();

    // ---- Phase B: expand spike bits * scalar, 256-bit stores ----
    const float scale = s_scale;
#pragma unroll 1
    for (int j = 0; j < ITERS; j++) {
        const int slab = blockIdx.x + j * GRID1 + half * 2048;
        const int n    = slab * HW + lane128 * 8;
        const uint32_t sbl = s_bits[j][threadIdx.x][0];
        const uint32_t sbh = s_bits[j][threadIdx.x][1];

#pragma unroll
        for (int t = 0; t < T_STEPS; t++) {
            float o[8];
#pragma unroll
            for (int e = 0; e < 4; e++)
                o[e]     = ((sbl >> (t + 8 * e)) & 1u) ? scale : 0.0f;
#pragma unroll
            for (int e = 0; e < 4; e++)
                o[e + 4] = ((sbh >> (t + 8 * e)) & 1u) ? scale : 0.0f;
            st256_resident(out + (size_t)t * N_ELEM + n, o);
        }
    }
}

// ---------------------------------------------------------------------------
extern "C" void kernel_launch(void* const* d_in, const int* in_sizes, int n_in,
                              void* d_out, int out_size) {
    const float* x      = (const float*)d_in[0];   // [T*B, C, H, W] fp32
    const float* thresh = (const float*)d_in[1];   // [1] fp32
    float*       out    = (float*)d_out;

    if_fused<<<GRID1, 256>>>(x, thresh, out);
}

// round 9
// speedup vs baseline: 1.0385x; 1.0385x over previous
#include <cuda_runtime.h>
#include <cstdint>

// Problem constants (fixed by the reference: T=8, x shape [T*32, 128, 32, 32])
#define T_STEPS   8
#define BATCH     32
#define CHANNELS  128
#define HW        1024                      // 32*32
#define N_ELEM    (BATCH*CHANNELS*HW)       // 4,194,304 spatial positions
#define GRID1     1024                      // single wave; all blocks co-resident
#define SLABS_PER_BLOCK 4                   // slabs b, b+1024, b+2048, b+3072 share channel b%128

// Scratch (static device globals — no runtime allocation permitted).
// Barrier counters are MONOTONIC across graph replays (each replay consumes
// exactly GRID1 arrivals / 1 release) -> no reset, fully deterministic.
__device__ float    g_partials[GRID1];
__device__ float    g_scale;
__device__ unsigned g_arrive  = 0;
__device__ unsigned g_release = 0;

// L2 policy hint for single-use streaming loads (128-bit, policy-register form).
__device__ __forceinline__ uint64_t make_policy_evict_first() {
    uint64_t p;
    asm("createpolicy.fractional.L2::evict_first.b64 %0, 1.0;" : "=l"(p));
    return p;
}
__device__ __forceinline__ float4 ld_stream(const float* p, uint64_t pol) {
    float4 v;
    asm volatile("ld.global.nc.L2::cache_hint.v4.f32 {%0,%1,%2,%3}, [%4], %5;"
                 : "=f"(v.x), "=f"(v.y), "=f"(v.z), "=f"(v.w)
                 : "l"(p), "l"(pol));
    return v;
}
// 256-bit store with direct evict_last modifier (v8 required for direct form).
__device__ __forceinline__ void st256_resident(float* p, const float* v) {
    asm volatile("st.global.L2::evict_last.v8.b32 [%0], {%1,%2,%3,%4,%5,%6,%7,%8};"
                 :: "l"(p),
                    "r"(__float_as_uint(v[0])), "r"(__float_as_uint(v[1])),
                    "r"(__float_as_uint(v[2])), "r"(__float_as_uint(v[3])),
                    "r"(__float_as_uint(v[4])), "r"(__float_as_uint(v[5])),
                    "r"(__float_as_uint(v[6])), "r"(__float_as_uint(v[7]))
                 : "memory");
}

// Block-wide deterministic sum (256 threads): shuffle tree + one smem hop.
__device__ __forceinline__ float block_sum_256(float v, float* ws) {
#pragma unroll
    for (int off = 16; off > 0; off >>= 1)
        v += __shfl_down_sync(0xFFFFFFFFu, v, off);
    const int wid = threadIdx.x >> 5;
    if ((threadIdx.x & 31) == 0) ws[wid] = v;
    __syncthreads();
    if (wid == 0) {
        v = (threadIdx.x < 8) ? ws[threadIdx.x] : 0.0f;
#pragma unroll
        for (int off = 4; off > 0; off >>= 1)
            v += __shfl_down_sync(0xFFFFFFFFu, v, off);
    }
    __syncthreads();
    return v;                 // valid in thread 0
}

// ---------------------------------------------------------------------------
// Fused persistent kernel: IF recurrence (128-bit loads, occ 7) -> grid
// barrier -> expansion with 256-bit stores (half the store instructions).
// ---------------------------------------------------------------------------
__global__ __launch_bounds__(256, 7) void if_fused(const float* __restrict__ x,
                                                   const float* __restrict__ thresh,
                                                   float* __restrict__ out) {
    __shared__ uint32_t s_bits[SLABS_PER_BLOCK][256];   // packed spike bytes, 4 KiB
    __shared__ float    s_ws[8];
    __shared__ float    s_scale;
    __shared__ unsigned s_gen;
    __shared__ int      s_last;

    const float    thre      = __ldg(thresh);
    const uint64_t pol_first = make_policy_evict_first();
    float local = 0.0f;

    // ---- Phase A: recurrence over 4 same-channel slabs (identical to R7) ----
#pragma unroll 1
    for (int k = 0; k < SLABS_PER_BLOCK; k++) {
        const int slab = blockIdx.x + k * GRID1;
        const int n    = slab * HW + threadIdx.x * 4;

        float4 xv[T_STEPS];
#pragma unroll
        for (int t = 0; t < T_STEPS; t++)
            xv[t] = ld_stream(x + (size_t)t * N_ELEM + n, pol_first);

        float    mem[4] = {0.5f * thre, 0.5f * thre, 0.5f * thre, 0.5f * thre};
        unsigned sb[4]  = {0u, 0u, 0u, 0u};

#pragma unroll
        for (int t = 0; t < T_STEPS; t++) {
            const float v[4] = {xv[t].x, xv[t].y, xv[t].z, xv[t].w};
#pragma unroll
            for (int j = 0; j < 4; j++) {
                mem[j] += v[j];
                if (mem[j] >= thre) {          // heaviside(mem - cur)
                    mem[j] -= thre;            // mem -= s*cur
                    sb[j]  |= (1u << t);
                }
            }
        }

        s_bits[k][threadIdx.x] = sb[0] | (sb[1] << 8) | (sb[2] << 16) | (sb[3] << 24);

        // Compensation pass -> per-element new_thre (cnt via popc).
#pragma unroll
        for (int j = 0; j < 4; j++) {
            const int   cnt = __popc(sb[j]);
            const float cv  = fminf((mem[j] - 0.5f * thre) + (float)cnt * thre,
                                    (float)T_STEPS * thre);
            if (cv > 0.0f && cnt > 0)
                local += cv / (float)cnt;
        }
    }

    const float total = block_sum_256(local, s_ws);

    // ---- Grid barrier (generation-counted, monotonic across replays) ----
    if (threadIdx.x == 0) {
        g_partials[blockIdx.x] = total;
        __threadfence();
        const unsigned old = atomicAdd(&g_arrive, 1u);
        s_gen  = old / GRID1;
        s_last = ((old % GRID1) == GRID1 - 1);
    }
    __syncthreads();

    if (s_last) {
        // Per-channel ub (channel = bid % 128, 8 partials each, fixed order),
        // masked diff, deterministic reduction -> scalar scale.
        float contrib = 0.0f;
        if (threadIdx.x < CHANNELS) {
            float s = 0.0f;
#pragma unroll
            for (int j = 0; j < GRID1 / CHANNELS; j++)
                s += g_partials[threadIdx.x + j * CHANNELS];
            const float ub = s / (float)(BATCH * HW);
            contrib = (thre > ub) ? (ub - thre) : 0.0f;
        }
        const float tot = block_sum_256(contrib, s_ws);
        if (threadIdx.x == 0) {
            g_scale = thre + 0.2f * tot / (float)CHANNELS;    // LR*2 = 0.2
            __threadfence();
            atomicAdd(&g_release, 1u);
        }
    }

    if (threadIdx.x == 0) {
        const unsigned target = s_gen + 1u;
        unsigned v;
        do {
            asm volatile("ld.acquire.gpu.u32 %0, [%1];" : "=r"(v) : "l"(&g_release));
        } while (v < target);
        s_scale = g_scale;
    }
    __syncthreads();

    // ---- Phase B: expansion with 256-bit stores ----
    // Threads split 128/128 across a slab pair; each thread owns 8 consecutive
    // elements, reading the two adjacent phase-A bit-words from smem.
    const float scale = s_scale;
    const int   tl    = threadIdx.x & 127;       // lane within slab (8 elems each)
    const int   sub   = threadIdx.x >> 7;        // which slab of the pair

#pragma unroll 1
    for (int kp = 0; kp < SLABS_PER_BLOCK; kp += 2) {
        const int      k    = kp + sub;
        const int      slab = blockIdx.x + k * GRID1;
        const int      n    = slab * HW + tl * 8;
        const uint32_t b0   = s_bits[k][tl * 2 + 0];    // elems n..n+3
        const uint32_t b1   = s_bits[k][tl * 2 + 1];    // elems n+4..n+7

#pragma unroll
        for (int t = 0; t < T_STEPS; t++) {
            float o[8];
#pragma unroll
            for (int e = 0; e < 4; e++)
                o[e]     = ((b0 >> (t + 8 * e)) & 1u) ? scale : 0.0f;
#pragma unroll
            for (int e = 0; e < 4; e++)
                o[e + 4] = ((b1 >> (t + 8 * e)) & 1u) ? scale : 0.0f;
            st256_resident(out + (size_t)t * N_ELEM + n, o);
        }
    }
}

// ---------------------------------------------------------------------------
extern "C" void kernel_launch(void* const* d_in, const int* in_sizes, int n_in,
                              void* d_out, int out_size) {
    const float* x      = (const float*)d_in[0];   // [T*B, C, H, W] fp32
    const float* thresh = (const float*)d_in[1];   // [1] fp32
    float*       out    = (float*)d_out;

    if_fused<<<GRID1, 256>>>(x, thresh, out);
}